// round 15
// baseline (speedup 1.0000x reference)
#include <cuda_runtime.h>

#define BB 4
#define DD 8
#define HH 512
#define WW 640
#define NB 16
#define HW (HH*WW)

#define PREP_CTAS 592   // 4 CTAs/SM on 148 SMs: leaves slots for main to co-reside under PDL

// Quad image: per pixel (v00, v01, v10, v11) with border clamp baked in.
// 4*512*640*16B = 20.97 MB static scratch (L2-resident).
__device__ float4 g_quad[BB*HW];

// Small-grid prep: grid-stride over 4-pixel chunks, float4 row loads.
// Only 592 CTAs -> main's CTAs get SM slots from t=0 and overlap their
// depth-load phase with prep's entire body (not just its drain tail).
__global__ void __launch_bounds__(256) prep_kernel(const float* __restrict__ ds) {
    // Allow the dependent main_kernel to begin launching immediately; it will
    // gridDependencySynchronize() before touching g_quad.
    cudaTriggerProgrammaticLaunchCompletion();

    int tid = blockIdx.x * 256 + threadIdx.x;
    for (int i = tid; i < BB*HW/4; i += PREP_CTAS*256) {
        int b  = i / (HW/4);
        int p4 = i - b*(HW/4);
        int y  = p4 / (WW/4);
        int x  = (p4 - y*(WW/4)) * 4;            // x in {0,4,...,636}

        const float* c = ds + (b*DD + DD/2)*HW;  // center plane (channel 4)
        int yp = (y + 1 < HH) ? y + 1 : HH - 1;
        const float* r0 = c + y*WW;
        const float* r1 = c + yp*WW;

        float4 a0 = __ldg((const float4*)(r0 + x));  // row y,   x..x+3 (16B-aligned)
        float4 a1 = __ldg((const float4*)(r1 + x));  // row y+1, x..x+3
        int x4 = (x + 4 < WW) ? x + 4 : WW - 1;      // border clamp for last quad
        float e0 = __ldg(r0 + x4);
        float e1 = __ldg(r1 + x4);

        float4* qo = g_quad + b*HW + y*WW + x;
        qo[0] = make_float4(a0.x, a0.y, a1.x, a1.y);
        qo[1] = make_float4(a0.y, a0.z, a1.y, a1.z);
        qo[2] = make_float4(a0.z, a0.w, a1.z, a1.w);
        qo[3] = make_float4(a0.w, e0,   a1.w, e1);
    }
}

// compare-exchange
#define CE(i,j) { float _lo = fminf(v[i], v[j]); v[j] = fmaxf(v[i], v[j]); v[i] = _lo; }

__global__ void __launch_bounds__(256) main_kernel(const float* __restrict__ ds,
                                                   const float* __restrict__ grid,
                                                   float* __restrict__ out) {
    int t = blockIdx.x * 256 + threadIdx.x;   // exactly BB*HW threads
    int b = t / HW;
    int p = t - b*HW;                          // p = y*WW + x

    float v[24];

    // 8 depth planes (streaming, evict-first) — independent of g_quad,
    // overlaps with prep_kernel under PDL.
    const float* dsp = ds + b*DD*HW + p;
    #pragma unroll
    for (int d = 0; d < DD; ++d) v[d] = __ldcs(dsp + d*HW);

    // Wait for prep_kernel to complete before reading g_quad.
    cudaGridDependencySynchronize();

    // 16 bilinear samples: one float2 grid read + one float4 quad gather each.
    const float2* g2 = (const float2*)grid + (size_t)b*NB*HW + p;
    const float4* q  = g_quad + b*HW;
    #pragma unroll
    for (int n = 0; n < NB; ++n) {
        float2 g = __ldcs(g2 + n*HW);
        float fx = fminf(fmaxf(fmaf(g.x, (float)(WW/2), (WW-1)*0.5f), 0.0f), (float)(WW-1));
        float fy = fminf(fmaxf(fmaf(g.y, (float)(HH/2), (HH-1)*0.5f), 0.0f), (float)(HH-1));
        int xi = (int)fx;                      // fx >= 0 -> trunc == floor
        int yi = (int)fy;
        float wx = fx - (float)xi;
        float wy = fy - (float)yi;
        float4 c = __ldcg(q + yi*WW + xi);     // single 16B gather, L2-direct
        float top = c.x + wx*(c.y - c.x);
        float bot = c.z + wx*(c.w - c.z);
        v[8 + n] = top + wy*(bot - top);
    }

    // ---- Batcher merge-exchange sorting network, n=24 (127 comparators) ----
    // p=16
    CE(0,16) CE(1,17) CE(2,18) CE(3,19) CE(4,20) CE(5,21) CE(6,22) CE(7,23)
    // p=8
    CE(0,8) CE(1,9) CE(2,10) CE(3,11) CE(4,12) CE(5,13) CE(6,14) CE(7,15)
    CE(8,16) CE(9,17) CE(10,18) CE(11,19) CE(12,20) CE(13,21) CE(14,22) CE(15,23)
    // p=4
    CE(0,4) CE(1,5) CE(2,6) CE(3,7) CE(8,12) CE(9,13) CE(10,14) CE(11,15)
    CE(16,20) CE(17,21) CE(18,22) CE(19,23)
    CE(4,16) CE(5,17) CE(6,18) CE(7,19)
    CE(4,8) CE(5,9) CE(6,10) CE(7,11) CE(12,16) CE(13,17) CE(14,18) CE(15,19)
    // p=2
    CE(0,2) CE(1,3) CE(4,6) CE(5,7) CE(8,10) CE(9,11) CE(12,14) CE(13,15)
    CE(16,18) CE(17,19) CE(20,22) CE(21,23)
    CE(2,16) CE(3,17) CE(6,20) CE(7,21)
    CE(2,8) CE(3,9) CE(6,12) CE(7,13) CE(10,16) CE(11,17) CE(14,20) CE(15,21)
    CE(2,4) CE(3,5) CE(6,8) CE(7,9) CE(10,12) CE(11,13) CE(14,16) CE(15,17)
    CE(18,20) CE(19,21)
    // p=1
    CE(0,1) CE(2,3) CE(4,5) CE(6,7) CE(8,9) CE(10,11) CE(12,13) CE(14,15)
    CE(16,17) CE(18,19) CE(20,21) CE(22,23)
    CE(1,16) CE(3,18) CE(5,20) CE(7,22)
    CE(1,8) CE(3,10) CE(5,12) CE(7,14) CE(9,16) CE(11,18) CE(13,20) CE(15,22)
    CE(1,4) CE(3,6) CE(5,8) CE(7,10) CE(9,12) CE(11,14) CE(13,16) CE(15,18)
    CE(17,20) CE(19,22)
    CE(1,2) CE(3,4) CE(5,6) CE(7,8) CE(9,10) CE(11,12) CE(13,14) CE(15,16)
    CE(17,18) CE(19,20) CE(21,22)

    // 24 coalesced streaming stores
    float* o = out + b*24*HW + p;
    #pragma unroll
    for (int k = 0; k < 24; ++k) __stcs(o + k*HW, v[k]);
}

extern "C" void kernel_launch(void* const* d_in, const int* in_sizes, int n_in,
                              void* d_out, int out_size) {
    // Identify tensors by element count:
    // depth_sample: 4*8*512*640 = 10485760, grid: 4*16*512*640*2 = 41943040
    const float* ds = nullptr;
    const float* grid = nullptr;
    for (int i = 0; i < n_in; ++i) {
        if (in_sizes[i] == BB*DD*HW)        ds   = (const float*)d_in[i];
        else if (in_sizes[i] == BB*NB*HW*2) grid = (const float*)d_in[i];
    }
    float* out = (float*)d_out;

    // Primary: small-grid prep (triggers programmatic completion at its start).
    prep_kernel<<<PREP_CTAS, 256>>>(ds);

    // Secondary: main, launched with Programmatic Stream Serialization so its
    // pre-gather phase overlaps prep's execution (now with real co-residency).
    cudaLaunchConfig_t cfg = {};
    cfg.gridDim = dim3((BB*HW)/256, 1, 1);
    cfg.blockDim = dim3(256, 1, 1);
    cfg.dynamicSmemBytes = 0;
    cfg.stream = 0;
    cudaLaunchAttribute attr[1];
    attr[0].id = cudaLaunchAttributeProgrammaticStreamSerialization;
    attr[0].val.programmaticStreamSerializationAllowed = 1;
    cfg.attrs = attr;
    cfg.numAttrs = 1;
    cudaLaunchKernelEx(&cfg, main_kernel, ds, grid, out);
}

// round 16
// speedup vs baseline: 1.0571x; 1.0571x over previous
#include <cuda_runtime.h>
#include <cuda_fp16.h>

#define BB 4
#define DD 8
#define HH 512
#define WW 640
#define NB 16
#define HW (HH*WW)

// Quad image in fp16: per pixel (v00,v01,v10,v11) packed as two half2 (8 bytes).
// Border clamp baked in. 4*512*640*8B = 10.5 MB (L2-resident), half the write
// traffic of the fp32 version -> prep is ~2x faster; gather wavefront count in
// main is unchanged (1 scattered line per sample either way).
__device__ uint2 g_quad[BB*HW];

__global__ void __launch_bounds__(256) prep_kernel(const float* __restrict__ ds) {
    // Allow the dependent main_kernel to begin launching immediately; it will
    // gridDependencySynchronize() before touching g_quad.
    cudaTriggerProgrammaticLaunchCompletion();

    int t = blockIdx.x * 256 + threadIdx.x;
    if (t >= BB*HW) return;
    int b = t / HW;
    int p = t - b*HW;
    int y = p / WW;
    int x = p - y*WW;
    const float* c = ds + (b*DD + DD/2)*HW;   // center plane (channel 4)
    int xp = (x + 1 < WW) ? x + 1 : WW - 1;
    int yp = (y + 1 < HH) ? y + 1 : HH - 1;
    float v00 = __ldg(c + y*WW + x);
    float v01 = __ldg(c + y*WW + xp);
    float v10 = __ldg(c + yp*WW + x);
    float v11 = __ldg(c + yp*WW + xp);
    __half2 h01 = __floats2half2_rn(v00, v01);
    __half2 h23 = __floats2half2_rn(v10, v11);
    uint2 q;
    q.x = *reinterpret_cast<unsigned*>(&h01);
    q.y = *reinterpret_cast<unsigned*>(&h23);
    g_quad[t] = q;
}

// compare-exchange
#define CE(i,j) { float _lo = fminf(v[i], v[j]); v[j] = fmaxf(v[i], v[j]); v[i] = _lo; }

__global__ void __launch_bounds__(256) main_kernel(const float* __restrict__ ds,
                                                   const float* __restrict__ grid,
                                                   float* __restrict__ out) {
    int t = blockIdx.x * 256 + threadIdx.x;   // exactly BB*HW threads
    int b = t / HW;
    int p = t - b*HW;                          // p = y*WW + x

    float v[24];

    // 8 depth planes (streaming, evict-first) — independent of g_quad,
    // overlaps with prep_kernel's tail under PDL.
    const float* dsp = ds + b*DD*HW + p;
    #pragma unroll
    for (int d = 0; d < DD; ++d) v[d] = __ldcs(dsp + d*HW);

    // Wait for prep_kernel to complete before reading g_quad.
    cudaGridDependencySynchronize();

    // 16 bilinear samples: one float2 grid read + one 8B quad gather each.
    const float2* g2 = (const float2*)grid + (size_t)b*NB*HW + p;
    const uint2*  q  = g_quad + b*HW;
    #pragma unroll
    for (int n = 0; n < NB; ++n) {
        float2 g = __ldcs(g2 + n*HW);
        float fx = fminf(fmaxf(fmaf(g.x, (float)(WW/2), (WW-1)*0.5f), 0.0f), (float)(WW-1));
        float fy = fminf(fmaxf(fmaf(g.y, (float)(HH/2), (HH-1)*0.5f), 0.0f), (float)(HH-1));
        int xi = (int)fx;                      // fx >= 0 -> trunc == floor
        int yi = (int)fy;
        float wx = fx - (float)xi;
        float wy = fy - (float)yi;
        uint2 cq = __ldcg(q + yi*WW + xi);     // single 8B gather, L2-direct
        float2 c01 = __half22float2(*reinterpret_cast<__half2*>(&cq.x)); // (v00,v01)
        float2 c23 = __half22float2(*reinterpret_cast<__half2*>(&cq.y)); // (v10,v11)
        float top = c01.x + wx*(c01.y - c01.x);
        float bot = c23.x + wx*(c23.y - c23.x);
        v[8 + n] = top + wy*(bot - top);
    }

    // ---- Batcher merge-exchange sorting network, n=24 (127 comparators) ----
    // p=16
    CE(0,16) CE(1,17) CE(2,18) CE(3,19) CE(4,20) CE(5,21) CE(6,22) CE(7,23)
    // p=8
    CE(0,8) CE(1,9) CE(2,10) CE(3,11) CE(4,12) CE(5,13) CE(6,14) CE(7,15)
    CE(8,16) CE(9,17) CE(10,18) CE(11,19) CE(12,20) CE(13,21) CE(14,22) CE(15,23)
    // p=4
    CE(0,4) CE(1,5) CE(2,6) CE(3,7) CE(8,12) CE(9,13) CE(10,14) CE(11,15)
    CE(16,20) CE(17,21) CE(18,22) CE(19,23)
    CE(4,16) CE(5,17) CE(6,18) CE(7,19)
    CE(4,8) CE(5,9) CE(6,10) CE(7,11) CE(12,16) CE(13,17) CE(14,18) CE(15,19)
    // p=2
    CE(0,2) CE(1,3) CE(4,6) CE(5,7) CE(8,10) CE(9,11) CE(12,14) CE(13,15)
    CE(16,18) CE(17,19) CE(20,22) CE(21,23)
    CE(2,16) CE(3,17) CE(6,20) CE(7,21)
    CE(2,8) CE(3,9) CE(6,12) CE(7,13) CE(10,16) CE(11,17) CE(14,20) CE(15,21)
    CE(2,4) CE(3,5) CE(6,8) CE(7,9) CE(10,12) CE(11,13) CE(14,16) CE(15,17)
    CE(18,20) CE(19,21)
    // p=1
    CE(0,1) CE(2,3) CE(4,5) CE(6,7) CE(8,9) CE(10,11) CE(12,13) CE(14,15)
    CE(16,17) CE(18,19) CE(20,21) CE(22,23)
    CE(1,16) CE(3,18) CE(5,20) CE(7,22)
    CE(1,8) CE(3,10) CE(5,12) CE(7,14) CE(9,16) CE(11,18) CE(13,20) CE(15,22)
    CE(1,4) CE(3,6) CE(5,8) CE(7,10) CE(9,12) CE(11,14) CE(13,16) CE(15,18)
    CE(17,20) CE(19,22)
    CE(1,2) CE(3,4) CE(5,6) CE(7,8) CE(9,10) CE(11,12) CE(13,14) CE(15,16)
    CE(17,18) CE(19,20) CE(21,22)

    // 24 coalesced streaming stores
    float* o = out + b*24*HW + p;
    #pragma unroll
    for (int k = 0; k < 24; ++k) __stcs(o + k*HW, v[k]);
}

extern "C" void kernel_launch(void* const* d_in, const int* in_sizes, int n_in,
                              void* d_out, int out_size) {
    // Identify tensors by element count:
    // depth_sample: 4*8*512*640 = 10485760, grid: 4*16*512*640*2 = 41943040
    const float* ds = nullptr;
    const float* grid = nullptr;
    for (int i = 0; i < n_in; ++i) {
        if (in_sizes[i] == BB*DD*HW)        ds   = (const float*)d_in[i];
        else if (in_sizes[i] == BB*NB*HW*2) grid = (const float*)d_in[i];
    }
    float* out = (float*)d_out;

    const int nblk = (BB*HW)/256;   // 5120

    // Primary: prep (triggers programmatic completion at its start).
    prep_kernel<<<nblk, 256>>>(ds);

    // Secondary: main, launched with Programmatic Stream Serialization so its
    // pre-gather phase overlaps prep's execution.
    cudaLaunchConfig_t cfg = {};
    cfg.gridDim = dim3(nblk, 1, 1);
    cfg.blockDim = dim3(256, 1, 1);
    cfg.dynamicSmemBytes = 0;
    cfg.stream = 0;
    cudaLaunchAttribute attr[1];
    attr[0].id = cudaLaunchAttributeProgrammaticStreamSerialization;
    attr[0].val.programmaticStreamSerializationAllowed = 1;
    cfg.attrs = attr;
    cfg.numAttrs = 1;
    cudaLaunchKernelEx(&cfg, main_kernel, ds, grid, out);
}

// round 17
// speedup vs baseline: 1.0794x; 1.0211x over previous
#include <cuda_runtime.h>
#include <cuda_fp16.h>

#define BB 4
#define DD 8
#define HH 512
#define WW 640
#define NB 16
#define HW (HH*WW)

// Quad image in fp16: per pixel (v00,v01,v10,v11) packed as two half2 (8 bytes).
// Border clamp baked in. 4*512*640*8B = 10.5 MB (L2-resident).
__device__ uint2 g_quad[BB*HW];

__device__ __forceinline__ unsigned pack_h2(float a, float b) {
    __half2 h = __floats2half2_rn(a, b);
    return *reinterpret_cast<unsigned*>(&h);
}

// 2px/thread prep: 2560 CTAs (half the launch/drain cost), one-shot.
// Reads rows y and y+1 around x..x+2, emits two 8B quads as one 16B store.
__global__ void __launch_bounds__(256) prep_kernel(const float* __restrict__ ds) {
    // Allow the dependent main_kernel to begin launching immediately; it will
    // gridDependencySynchronize() before touching g_quad.
    cudaTriggerProgrammaticLaunchCompletion();

    int t = blockIdx.x * 256 + threadIdx.x;      // BB*HW/2 threads
    int b  = t / (HW/2);
    int p2 = t - b*(HW/2);
    int y  = p2 / (WW/2);
    int x  = (p2 - y*(WW/2)) * 2;                // x in {0,2,...,638}

    const float* c = ds + (b*DD + DD/2)*HW;      // center plane (channel 4)
    int yp = (y + 1 < HH) ? y + 1 : HH - 1;
    const float* r0 = c + y*WW;
    const float* r1 = c + yp*WW;

    // pixels x and x+1 need columns x, x+1, x+2 (clamped)
    float2 a0 = __ldg((const float2*)(r0 + x));  // 8B-aligned (x even)
    float2 a1 = __ldg((const float2*)(r1 + x));
    int x2 = (x + 2 < WW) ? x + 2 : WW - 1;
    float e0 = __ldg(r0 + x2);
    float e1 = __ldg(r1 + x2);

    uint4 q;
    q.x = pack_h2(a0.x, a0.y);   // px x:   v00,v01
    q.y = pack_h2(a1.x, a1.y);   // px x:   v10,v11
    q.z = pack_h2(a0.y, e0);     // px x+1: v00,v01
    q.w = pack_h2(a1.y, e1);     // px x+1: v10,v11
    *reinterpret_cast<uint4*>(g_quad + b*HW + y*WW + x) = q;
}

// compare-exchange
#define CE(i,j) { float _lo = fminf(v[i], v[j]); v[j] = fmaxf(v[i], v[j]); v[i] = _lo; }

__global__ void __launch_bounds__(256) main_kernel(const float* __restrict__ ds,
                                                   const float* __restrict__ grid,
                                                   float* __restrict__ out) {
    int t = blockIdx.x * 256 + threadIdx.x;   // exactly BB*HW threads
    int b = t / HW;
    int p = t - b*HW;                          // p = y*WW + x

    float v[24];

    // 8 depth planes (streaming, evict-first) — independent of g_quad,
    // overlaps with prep_kernel's tail under PDL.
    const float* dsp = ds + b*DD*HW + p;
    #pragma unroll
    for (int d = 0; d < DD; ++d) v[d] = __ldcs(dsp + d*HW);

    // Wait for prep_kernel to complete before reading g_quad.
    cudaGridDependencySynchronize();

    // 16 bilinear samples: one float2 grid read + one 8B quad gather each.
    const float2* g2 = (const float2*)grid + (size_t)b*NB*HW + p;
    const uint2*  q  = g_quad + b*HW;
    #pragma unroll
    for (int n = 0; n < NB; ++n) {
        float2 g = __ldcs(g2 + n*HW);
        float fx = fminf(fmaxf(fmaf(g.x, (float)(WW/2), (WW-1)*0.5f), 0.0f), (float)(WW-1));
        float fy = fminf(fmaxf(fmaf(g.y, (float)(HH/2), (HH-1)*0.5f), 0.0f), (float)(HH-1));
        int xi = (int)fx;                      // fx >= 0 -> trunc == floor
        int yi = (int)fy;
        float wx = fx - (float)xi;
        float wy = fy - (float)yi;
        uint2 cq = __ldcg(q + yi*WW + xi);     // single 8B gather, L2-direct
        float2 c01 = __half22float2(*reinterpret_cast<__half2*>(&cq.x)); // (v00,v01)
        float2 c23 = __half22float2(*reinterpret_cast<__half2*>(&cq.y)); // (v10,v11)
        float top = c01.x + wx*(c01.y - c01.x);
        float bot = c23.x + wx*(c23.y - c23.x);
        v[8 + n] = top + wy*(bot - top);
    }

    // ---- Batcher merge-exchange sorting network, n=24 (127 comparators) ----
    // p=16
    CE(0,16) CE(1,17) CE(2,18) CE(3,19) CE(4,20) CE(5,21) CE(6,22) CE(7,23)
    // p=8
    CE(0,8) CE(1,9) CE(2,10) CE(3,11) CE(4,12) CE(5,13) CE(6,14) CE(7,15)
    CE(8,16) CE(9,17) CE(10,18) CE(11,19) CE(12,20) CE(13,21) CE(14,22) CE(15,23)
    // p=4
    CE(0,4) CE(1,5) CE(2,6) CE(3,7) CE(8,12) CE(9,13) CE(10,14) CE(11,15)
    CE(16,20) CE(17,21) CE(18,22) CE(19,23)
    CE(4,16) CE(5,17) CE(6,18) CE(7,19)
    CE(4,8) CE(5,9) CE(6,10) CE(7,11) CE(12,16) CE(13,17) CE(14,18) CE(15,19)
    // p=2
    CE(0,2) CE(1,3) CE(4,6) CE(5,7) CE(8,10) CE(9,11) CE(12,14) CE(13,15)
    CE(16,18) CE(17,19) CE(20,22) CE(21,23)
    CE(2,16) CE(3,17) CE(6,20) CE(7,21)
    CE(2,8) CE(3,9) CE(6,12) CE(7,13) CE(10,16) CE(11,17) CE(14,20) CE(15,21)
    CE(2,4) CE(3,5) CE(6,8) CE(7,9) CE(10,12) CE(11,13) CE(14,16) CE(15,17)
    CE(18,20) CE(19,21)
    // p=1
    CE(0,1) CE(2,3) CE(4,5) CE(6,7) CE(8,9) CE(10,11) CE(12,13) CE(14,15)
    CE(16,17) CE(18,19) CE(20,21) CE(22,23)
    CE(1,16) CE(3,18) CE(5,20) CE(7,22)
    CE(1,8) CE(3,10) CE(5,12) CE(7,14) CE(9,16) CE(11,18) CE(13,20) CE(15,22)
    CE(1,4) CE(3,6) CE(5,8) CE(7,10) CE(9,12) CE(11,14) CE(13,16) CE(15,18)
    CE(17,20) CE(19,22)
    CE(1,2) CE(3,4) CE(5,6) CE(7,8) CE(9,10) CE(11,12) CE(13,14) CE(15,16)
    CE(17,18) CE(19,20) CE(21,22)

    // 24 coalesced streaming stores
    float* o = out + b*24*HW + p;
    #pragma unroll
    for (int k = 0; k < 24; ++k) __stcs(o + k*HW, v[k]);
}

extern "C" void kernel_launch(void* const* d_in, const int* in_sizes, int n_in,
                              void* d_out, int out_size) {
    // Identify tensors by element count:
    // depth_sample: 4*8*512*640 = 10485760, grid: 4*16*512*640*2 = 41943040
    const float* ds = nullptr;
    const float* grid = nullptr;
    for (int i = 0; i < n_in; ++i) {
        if (in_sizes[i] == BB*DD*HW)        ds   = (const float*)d_in[i];
        else if (in_sizes[i] == BB*NB*HW*2) grid = (const float*)d_in[i];
    }
    float* out = (float*)d_out;

    // Primary: 2px/thread prep, 2560 CTAs (triggers programmatic completion).
    prep_kernel<<<(BB*HW/2)/256, 256>>>(ds);

    // Secondary: main, launched with Programmatic Stream Serialization so its
    // pre-gather phase overlaps prep's execution.
    cudaLaunchConfig_t cfg = {};
    cfg.gridDim = dim3((BB*HW)/256, 1, 1);
    cfg.blockDim = dim3(256, 1, 1);
    cfg.dynamicSmemBytes = 0;
    cfg.stream = 0;
    cudaLaunchAttribute attr[1];
    attr[0].id = cudaLaunchAttributeProgrammaticStreamSerialization;
    attr[0].val.programmaticStreamSerializationAllowed = 1;
    cfg.attrs = attr;
    cfg.numAttrs = 1;
    cudaLaunchKernelEx(&cfg, main_kernel, ds, grid, out);
}